// round 3
// baseline (speedup 1.0000x reference)
#include <cuda_runtime.h>
#include <math.h>

// Problem constants
#define B_  2
#define S_  2048
#define D_  1024
#define H_  16
#define L_  512
#define DH_ 64
#define NTOK (B_*S_)          // 4096

// ---------------- scratch (device globals) --------------------------------------
__device__ float g_c   [NTOK * L_];
__device__ float g_ckv [NTOK * L_];
__device__ float g_ak  [D_ * L_];
__device__ float g_tmp [(size_t)B_ * S_ * H_ * L_];
__device__ float g_sc  [(size_t)B_ * H_ * S_ * S_];
__device__ float g_v   [NTOK * D_];
__device__ float g_ctx [NTOK * D_];

// ---------------- tf32 helpers ---------------------------------------------------
__device__ __forceinline__ unsigned f2tf(float f) {
    unsigned u;
    asm("cvt.rna.tf32.f32 %0, %1;" : "=r"(u) : "f"(f));
    return u;
}

__device__ __forceinline__ void mma_tf32(float (&c)[4], const unsigned (&a)[4],
                                         const unsigned (&b)[2]) {
    asm volatile(
        "mma.sync.aligned.m16n8k8.row.col.f32.tf32.tf32.f32 "
        "{%0,%1,%2,%3}, {%4,%5,%6,%7}, {%8,%9}, {%0,%1,%2,%3};"
        : "+f"(c[0]), "+f"(c[1]), "+f"(c[2]), "+f"(c[3])
        : "r"(a[0]), "r"(a[1]), "r"(a[2]), "r"(a[3]), "r"(b[0]), "r"(b[1]));
}

// ---------------- tf32 tensor-core GEMM, fragment-major smem ---------------------
// C[m,n] = alpha * sum_k A[m,k] * (BT ? B[n,k] : B[k,n])
// 256 threads = 8 warps (2 in M x 4 in N). Warp tile (BM/2) x (BN/4).
// Smem holds tf32-converted tiles. A (and B when BT) are stored in mma-fragment
// order: within each 16x8 (A) / 8x8 (B) tile, slot = (k&3)*8 + (m|n & 7), so a
// warp fragment load is a single LDS.128 (A) / LDS.64 (B), conflict-free.
// Double-buffered, one __syncthreads per BK=16 k-tile, register prefetch.
// CAUSAL: 0 none, 1 skip blocks with n0 > m0+BM-1, 2 clamp K to m0+BM.
template<int BM, int BN, bool BT, int CAUSAL>
__global__ __launch_bounds__(256, 2)
void mma_gemm(const float* __restrict__ A, const float* __restrict__ B,
              float* __restrict__ C,
              int M, int N, int K, int lda, int ldb, int ldc,
              long sA1, long sA2, long sB1, long sB2, long sC1, long sC2,
              int zdiv, float alpha)
{
    constexpr int BK = 16;
    constexpr int KT = BK / 8;          // 2 k8-steps per tile
    constexpr int MT = BM / 32;         // m16 tiles per warp
    constexpr int NT = BN / 32;         // n8 tiles per warp
    constexpr int LA = BM * BK / (4 * 256);
    constexpr int LB = BN * BK / (4 * 256);
    constexpr int ASZ = BM * BK;                        // frag-major
    constexpr int BSZ = BT ? (BN * BK) : (BK * (BN + 4));

    const int z = blockIdx.z;
    const int zhi = z / zdiv, zlo = z % zdiv;
    A += (long)zhi * sA1 + (long)zlo * sA2;
    B += (long)zhi * sB1 + (long)zlo * sB2;
    C += (long)zhi * sC1 + (long)zlo * sC2;

    const int m0 = blockIdx.y * BM;
    const int n0 = blockIdx.x * BN;
    if (CAUSAL == 1 && n0 > m0 + BM - 1) return;
    int Keff = K;
    if (CAUSAL == 2) Keff = min(K, m0 + BM);

    __shared__ unsigned As[2][ASZ];
    __shared__ unsigned Bs[2][BSZ];

    const int tid  = threadIdx.x;
    const int warp = tid >> 5;
    const int lane = tid & 31;
    const int gid  = lane >> 2;
    const int tig  = lane & 3;
    const int wm0  = (warp & 1) * (BM / 2);
    const int wn0  = (warp >> 1) * (BN / 4);
    const int mtb  = wm0 >> 4;          // first m16-tile of this warp
    const int tnb  = wn0 >> 3;          // first n8-tile of this warp
    const unsigned slotA = (unsigned)(tig * 8 + gid) * 4;
    const unsigned slotB = (unsigned)(tig * 8 + gid) * 2;

    float acc[MT][NT][4];
    #pragma unroll
    for (int i = 0; i < MT; i++)
        #pragma unroll
        for (int j = 0; j < NT; j++)
            #pragma unroll
            for (int r = 0; r < 4; r++) acc[i][j][r] = 0.f;

    float4 pa[LA], pb[LB];

    // precomputed loader coordinates
    int a_row[LA], a_kq[LA];
    #pragma unroll
    for (int i = 0; i < LA; i++) { int f = tid + i*256; a_row[i] = f >> 2; a_kq[i] = (f & 3) * 4; }
    int b_r0[LB], b_c0[LB];
    #pragma unroll
    for (int i = 0; i < LB; i++) {
        int f = tid + i*256;
        if (BT) { b_r0[i] = f >> 2;            b_c0[i] = (f & 3) * 4; }          // n, kq
        else    { b_r0[i] = f / (BN/4);        b_c0[i] = (f % (BN/4)) * 4; }     // k, nq
    }

    auto load_g = [&](int k0) {
        #pragma unroll
        for (int i = 0; i < LA; i++)
            pa[i] = *(const float4*)&A[(long)(m0 + a_row[i]) * lda + k0 + a_kq[i]];
        #pragma unroll
        for (int i = 0; i < LB; i++) {
            if (BT) pb[i] = *(const float4*)&B[(long)(n0 + b_r0[i]) * ldb + k0 + b_c0[i]];
            else    pb[i] = *(const float4*)&B[(long)(k0 + b_r0[i]) * ldb + n0 + b_c0[i]];
        }
    };

    auto store_s = [&](int buf) {
        #pragma unroll
        for (int i = 0; i < LA; i++) {
            int row = a_row[i], kq = a_kq[i];
            int mt    = row >> 4;
            int ktile = kq >> 3;
            int reg   = ((row >> 3) & 1) + ((kq >> 2) & 1) * 2;
            unsigned base = (unsigned)((mt * KT + ktile) * 128 + (row & 7) * 4 + reg);
            As[buf][base +  0] = f2tf(pa[i].x);
            As[buf][base + 32] = f2tf(pa[i].y);
            As[buf][base + 64] = f2tf(pa[i].z);
            As[buf][base + 96] = f2tf(pa[i].w);
        }
        #pragma unroll
        for (int i = 0; i < LB; i++) {
            if (BT) {
                int row = b_r0[i], kq = b_c0[i];
                int tn    = row >> 3;
                int ktile = kq >> 3;
                int reg   = (kq >> 2) & 1;
                unsigned base = (unsigned)((tn * KT + ktile) * 64 + (row & 7) * 2 + reg);
                Bs[buf][base +  0] = f2tf(pb[i].x);
                Bs[buf][base + 16] = f2tf(pb[i].y);
                Bs[buf][base + 32] = f2tf(pb[i].z);
                Bs[buf][base + 48] = f2tf(pb[i].w);
            } else {
                unsigned idx = (unsigned)(b_r0[i] * (BN + 4) + b_c0[i]);
                uint4 v;
                v.x = f2tf(pb[i].x); v.y = f2tf(pb[i].y);
                v.z = f2tf(pb[i].z); v.w = f2tf(pb[i].w);
                *(uint4*)&Bs[buf][idx] = v;
            }
        }
    };

    const int T = Keff / BK;
    load_g(0);
    store_s(0);
    __syncthreads();

    for (int t = 0; t < T; t++) {
        const int cur = t & 1;
        if (t + 1 < T) load_g((t + 1) * BK);

        #pragma unroll
        for (int kt = 0; kt < KT; kt++) {
            unsigned a[MT][4];
            #pragma unroll
            for (int mt = 0; mt < MT; mt++) {
                uint4 av = *(const uint4*)&As[cur][(unsigned)(((mtb + mt) * KT + kt) * 128) + slotA];
                a[mt][0] = av.x; a[mt][1] = av.y; a[mt][2] = av.z; a[mt][3] = av.w;
            }
            unsigned b[NT][2];
            #pragma unroll
            for (int nt = 0; nt < NT; nt++) {
                if (BT) {
                    uint2 bv = *(const uint2*)&Bs[cur][(unsigned)(((tnb + nt) * KT + kt) * 64) + slotB];
                    b[nt][0] = bv.x; b[nt][1] = bv.y;
                } else {
                    int cidx = wn0 + nt * 8 + gid;
                    b[nt][0] = Bs[cur][(kt * 8 + tig    ) * (BN + 4) + cidx];
                    b[nt][1] = Bs[cur][(kt * 8 + tig + 4) * (BN + 4) + cidx];
                }
            }
            #pragma unroll
            for (int mt = 0; mt < MT; mt++)
                #pragma unroll
                for (int nt = 0; nt < NT; nt++)
                    mma_tf32(acc[mt][nt], a[mt], b[nt]);
        }

        if (t + 1 < T) store_s((t + 1) & 1);
        __syncthreads();
    }

    // ---- writeback ----
    #pragma unroll
    for (int mt = 0; mt < MT; mt++) {
        int r0 = m0 + wm0 + mt * 16 + gid;
        #pragma unroll
        for (int nt = 0; nt < NT; nt++) {
            int cc = n0 + wn0 + nt * 8 + tig * 2;
            float2 v0 = make_float2(acc[mt][nt][0] * alpha, acc[mt][nt][1] * alpha);
            float2 v1 = make_float2(acc[mt][nt][2] * alpha, acc[mt][nt][3] * alpha);
            *(float2*)&C[(long)r0 * ldc + cc]       = v0;
            *(float2*)&C[(long)(r0 + 8) * ldc + cc] = v1;
        }
    }
}

// ---------------- LayerNorm over L=512 ------------------------------------------
__global__ __launch_bounds__(256)
void ln_k(const float* __restrict__ c, float* __restrict__ ckv,
          float* __restrict__ out2,
          const float* __restrict__ gamma, const float* __restrict__ beta)
{
    __shared__ float red[256];
    const int r   = blockIdx.x;
    const int tid = threadIdx.x;
    const float* row = c + (long)r * L_;

    float a0 = row[tid], a1 = row[tid + 256];

    red[tid] = a0 + a1; __syncthreads();
    for (int s = 128; s > 0; s >>= 1) { if (tid < s) red[tid] += red[tid+s]; __syncthreads(); }
    float mu = red[0] * (1.0f / L_); __syncthreads();

    float d0 = a0 - mu, d1 = a1 - mu;
    red[tid] = d0*d0 + d1*d1; __syncthreads();
    for (int s = 128; s > 0; s >>= 1) { if (tid < s) red[tid] += red[tid+s]; __syncthreads(); }
    float rstd = rsqrtf(red[0] * (1.0f / L_) + 1e-5f);

    float y0 = d0 * rstd * gamma[tid]       + beta[tid];
    float y1 = d1 * rstd * gamma[tid + 256] + beta[tid + 256];

    long o = (long)r * L_;
    ckv[o + tid] = y0; ckv[o + tid + 256] = y1;
    if (out2) { out2[o + tid] = y0; out2[o + tid + 256] = y1; }
}

// ---------------- causal softmax over t, in place --------------------------------
__global__ __launch_bounds__(256)
void softmax_k(float* __restrict__ sc)
{
    __shared__ float red[256];
    const long r  = blockIdx.x;
    const int  s  = (int)(r % S_);
    const int tid = threadIdx.x;
    float* row = sc + r * (long)S_;

    float v[8];
    float mx = -INFINITY;
    #pragma unroll
    for (int i = 0; i < 8; i++) {
        int t = tid + i*256;
        v[i] = (t <= s) ? row[t] : -INFINITY;
        mx = fmaxf(mx, v[i]);
    }
    red[tid] = mx; __syncthreads();
    for (int k = 128; k > 0; k >>= 1) { if (tid < k) red[tid] = fmaxf(red[tid], red[tid+k]); __syncthreads(); }
    mx = red[0]; __syncthreads();

    float sum = 0.f;
    #pragma unroll
    for (int i = 0; i < 8; i++) {
        int t = tid + i*256;
        v[i] = (t <= s) ? __expf(v[i] - mx) : 0.f;
        sum += v[i];
    }
    red[tid] = sum; __syncthreads();
    for (int k = 128; k > 0; k >>= 1) { if (tid < k) red[tid] += red[tid+k]; __syncthreads(); }
    float inv = 1.0f / red[0];

    const int bound = ((s >> 7) + 1) << 7;   // zero-fill through the 128-wide diag tile
    #pragma unroll
    for (int i = 0; i < 8; i++) {
        int t = tid + i*256;
        if (t < bound) row[t] = (t <= s) ? v[i] * inv : 0.f;
    }
}

// ---------------- launch ---------------------------------------------------------
extern "C" void kernel_launch(void* const* d_in, const int* in_sizes, int n_in,
                              void* d_out, int out_size)
{
    const float* x      = (const float*)d_in[0];
    const float* W_q    = (const float*)d_in[1];
    const float* W_dkv  = (const float*)d_in[2];
    const float* W_uk   = (const float*)d_in[3];
    const float* W_uv   = (const float*)d_in[4];
    const float* W_o    = (const float*)d_in[5];
    const float* gamma  = (const float*)d_in[6];
    const float* beta   = (const float*)d_in[7];
    float* out = (float*)d_out;

    float *c, *ckv, *ak, *tmp, *sc, *v, *ctx;
    cudaGetSymbolAddress((void**)&c,   g_c);
    cudaGetSymbolAddress((void**)&ckv, g_ckv);
    cudaGetSymbolAddress((void**)&ak,  g_ak);
    cudaGetSymbolAddress((void**)&tmp, g_tmp);
    cudaGetSymbolAddress((void**)&sc,  g_sc);
    cudaGetSymbolAddress((void**)&v,   g_v);
    cudaGetSymbolAddress((void**)&ctx, g_ctx);

    float* out_ckv = (out_size >= NTOK*D_ + NTOK*L_) ? out + (long)NTOK*D_ : nullptr;

    const dim3 blk(256);

    // K1: c = x @ W_dkv^T   [4096,512]
    mma_gemm<128,128,true,0><<<dim3(L_/128, NTOK/128, 1), blk>>>(
        x, W_dkv, c, NTOK, L_, D_, D_, D_, L_,
        0,0, 0,0, 0,0, 16, 1.0f);

    // K2: LayerNorm -> c_kv (and second output)
    ln_k<<<NTOK, 256>>>(c, ckv, out_ckv, gamma, beta);

    // K3: absorbed_k = W_q @ W_uk   [1024,512]
    mma_gemm<128,128,false,0><<<dim3(L_/128, D_/128, 1), blk>>>(
        W_q, W_uk, ak, D_, L_, D_, D_, L_, L_,
        0,0, 0,0, 0,0, 16, 1.0f);

    // K4: tmp[b,s,h,:] = x[b,s,h*64:+64] @ ak[h]   (batched over h)
    mma_gemm<128,128,false,0><<<dim3(L_/128, NTOK/128, H_), blk>>>(
        x, ak, tmp, NTOK, L_, DH_, D_, L_, H_*L_,
        0, DH_,
        0, (long)DH_*L_,
        0, L_,
        16, 1.0f);

    // K5: scores = tmp @ c_kv^T / 8   (batched over b,h; causal block skip)
    mma_gemm<128,128,true,1><<<dim3(S_/128, S_/128, B_*H_), blk>>>(
        tmp, ckv, sc, S_, S_, L_, H_*L_, L_, S_,
        (long)S_*H_*L_, (long)L_,
        (long)S_*L_,    0,
        (long)H_*S_*S_, (long)S_*S_,
        H_, 0.125f);

    // K6: causal softmax, in place
    softmax_k<<<B_*H_*S_, 256>>>(sc);

    // K7: v = c_kv @ W_uv^T   [4096,1024]
    mma_gemm<128,128,true,0><<<dim3(D_/128, NTOK/128, 1), blk>>>(
        ckv, W_uv, v, NTOK, D_, L_, L_, L_, D_,
        0,0, 0,0, 0,0, 16, 1.0f);

    // K8: ctx[b,:,h,:] = attn @ v[b,:,h,:]   (batched over b,h; K clamped causally)
    mma_gemm<128,64,false,2><<<dim3(1, S_/128, B_*H_), blk>>>(
        sc, v, ctx, S_, DH_, S_, S_, D_, D_,
        (long)H_*S_*S_, (long)S_*S_,
        (long)S_*D_,    (long)DH_,
        (long)S_*D_,    (long)DH_,
        H_, 1.0f);

    // K9: out = ctx @ W_o^T
    mma_gemm<128,128,true,0><<<dim3(D_/128, NTOK/128, 1), blk>>>(
        ctx, W_o, out, NTOK, D_, D_, D_, D_, D_,
        0,0, 0,0, 0,0, 16, 1.0f);
}

// round 6
// speedup vs baseline: 1.4362x; 1.4362x over previous
#include <cuda_runtime.h>
#include <math.h>
#include <stdint.h>

// Problem constants
#define B_  2
#define S_  2048
#define D_  1024
#define H_  16
#define L_  512
#define DH_ 64
#define NTOK (B_*S_)          // 4096

// ---------------- scratch (device globals) --------------------------------------
__device__ float g_c   [NTOK * L_];                 // pre-LN latent
__device__ float g_ckv [NTOK * L_];                 // LayerNormed latent
__device__ float g_akT [L_ * D_];                   // absorbed K, transposed [L, D]
__device__ float g_tmp [(size_t)B_ * S_ * H_ * L_]; // q_eff [B,S,H,L]
__device__ float g_sc  [(size_t)B_ * H_ * S_ * S_]; // scores/attn
__device__ float g_vT  [(size_t)D_ * NTOK];         // values transposed [D, NTOK]
__device__ float g_ctx [NTOK * D_];                 // context

// ---------------- helpers ---------------------------------------------------------
__device__ __forceinline__ uint32_t s2u(const void* p) {
    uint32_t a;
    asm("{ .reg .u64 t; cvta.to.shared.u64 t, %1; cvt.u32.u64 %0, t; }"
        : "=r"(a) : "l"(p));
    return a;
}
__device__ __forceinline__ unsigned f2tf(float f) {
    unsigned u;
    asm("cvt.rna.tf32.f32 %0, %1;" : "=r"(u) : "f"(f));
    return u;
}
__device__ __forceinline__ void ldm_x4(unsigned &r0, unsigned &r1, unsigned &r2,
                                       unsigned &r3, uint32_t addr) {
    asm volatile("ldmatrix.sync.aligned.m8n8.x4.shared.b16 {%0,%1,%2,%3}, [%4];"
                 : "=r"(r0), "=r"(r1), "=r"(r2), "=r"(r3) : "r"(addr));
}
__device__ __forceinline__ void mma_tf32(float (&c)[4], const unsigned (&a)[4],
                                         const unsigned (&b)[2]) {
    asm volatile(
        "mma.sync.aligned.m16n8k8.row.col.f32.tf32.tf32.f32 "
        "{%0,%1,%2,%3}, {%4,%5,%6,%7}, {%8,%9}, {%0,%1,%2,%3};"
        : "+f"(c[0]), "+f"(c[1]), "+f"(c[2]), "+f"(c[3])
        : "r"(a[0]), "r"(a[1]), "r"(a[2]), "r"(a[3]), "r"(b[0]), "r"(b[1]));
}

// ---------------- tf32 mma.sync GEMM with ldmatrix feeding ------------------------
// C[m,n] = alpha * sum_k A[m,k] * B'[n,k]
//   BT=true : B given as [N,K] K-major. BT=false: B given as [K,N] (transpose-load).
// CT=true: store C transposed (C[n*ldc + m]).
// CAUSAL: 0 none, 1 skip blocks n0 > m0+BM-1 (QK^T), 2 clamp K to m0+BM (attn@V).
// BM=128, BK=32, 256 threads = 8 warps (2M x 4N). Warp tile 64 x (BN/4).
// Smem tiles are K-major [row][32+4] tf32 words; fragments come via ldmatrix.x4.b16
// (8x8 b16 matrix == 8x4 tf32 matrix; lane mapping matches tf32 mma fragments).
template<int BN, bool BT, int CAUSAL, bool CT>
__global__ __launch_bounds__(256, 2)
void tc_gemm(const float* __restrict__ A, const float* __restrict__ B,
             float* __restrict__ C,
             int M, int N, int K, int lda, int ldb, int ldc,
             long sA1, long sA2, long sB1, long sB2, long sC1, long sC2,
             int zdiv, float alpha)
{
    constexpr int BM = 128, BK = 32, RW = BK + 4;     // padded row: 36 words
    constexpr int MT = 4;                             // m16 tiles per warp (64 rows)
    constexpr int NT = BN / 32;                       // n8 tiles per warp
    constexpr int NG = NT / 2;                        // n16 ldmatrix groups
    constexpr int LA = BM * BK / (4 * 256);           // 4 float4/thread
    constexpr int LB = BN * BK / (4 * 256);           // 4 or 2
    constexpr int ASZ = BM * RW;                      // words per A buffer
    constexpr int BSZ = BN * RW;

    extern __shared__ __align__(16) unsigned sm[];

    const int z = blockIdx.z;
    const int zhi = z / zdiv, zlo = z % zdiv;
    A += (long)zhi * sA1 + (long)zlo * sA2;
    B += (long)zhi * sB1 + (long)zlo * sB2;
    C += (long)zhi * sC1 + (long)zlo * sC2;

    const int m0 = blockIdx.y * BM;
    const int n0 = blockIdx.x * BN;
    if (CAUSAL == 1 && n0 > m0 + BM - 1) return;
    int Keff = K;
    if (CAUSAL == 2) Keff = min(K, m0 + BM);

    const int tid  = threadIdx.x;
    const int warp = tid >> 5;
    const int lane = tid & 31;
    const int gid  = lane >> 2;
    const int tig  = lane & 3;
    const int wm0  = (warp & 1) * 64;                 // warp row base
    const int wn0  = (warp >> 1) * (BN / 4);          // warp col base

    // ldmatrix lane->row mapping: matrix idx = lane>>3; row in matrix = lane&7.
    // mat 0: rows+0 colsK 0-3 | mat 1: rows+8 colsK 0-3 | mat 2: rows+0 colsK 4-7 | mat 3: rows+8 colsK 4-7
    const uint32_t lrow = ((lane >> 3) & 1) * 8 + (lane & 7);
    const uint32_t lcol = (lane >> 4) * 4;
    const uint32_t laneA = (uint32_t)(wm0 + lrow) * RW + lcol;   // word offset
    const uint32_t laneB = (uint32_t)(wn0 + lrow) * RW + lcol;

    const uint32_t smu = s2u(sm);
    // layout: As0 As1 Bs0 Bs1
    unsigned* const aBuf[2] = { sm,            sm + ASZ };
    unsigned* const bBuf[2] = { sm + 2*ASZ,    sm + 2*ASZ + BSZ };
    const uint32_t aAdr[2]  = { smu,           smu + ASZ*4 };
    const uint32_t bAdr[2]  = { smu + 2*ASZ*4, smu + (2*ASZ + BSZ)*4 };

    float acc[MT][NT][4];
    #pragma unroll
    for (int i = 0; i < MT; i++)
        #pragma unroll
        for (int j = 0; j < NT; j++)
            #pragma unroll
            for (int r = 0; r < 4; r++) acc[i][j][r] = 0.f;

    float4 pa[LA], pb[LB];

    auto load_g = [&](int k0) {
        #pragma unroll
        for (int i = 0; i < LA; i++) {
            int f = tid + i * 256;
            pa[i] = *(const float4*)&A[(long)(m0 + (f >> 3)) * lda + k0 + (f & 7) * 4];
        }
        #pragma unroll
        for (int i = 0; i < LB; i++) {
            int f = tid + i * 256;
            if (BT) pb[i] = *(const float4*)&B[(long)(n0 + (f >> 3)) * ldb + k0 + (f & 7) * 4];
            else    pb[i] = *(const float4*)&B[(long)(k0 + (f & 31)) * ldb + n0 + (f >> 5) * 4];
        }
    };
    auto store_s = [&](int buf) {
        #pragma unroll
        for (int i = 0; i < LA; i++) {
            int f = tid + i * 256;
            uint4 u;
            u.x = f2tf(pa[i].x); u.y = f2tf(pa[i].y);
            u.z = f2tf(pa[i].z); u.w = f2tf(pa[i].w);
            *(uint4*)&aBuf[buf][(f >> 3) * RW + (f & 7) * 4] = u;
        }
        #pragma unroll
        for (int i = 0; i < LB; i++) {
            int f = tid + i * 256;
            if (BT) {
                uint4 u;
                u.x = f2tf(pb[i].x); u.y = f2tf(pb[i].y);
                u.z = f2tf(pb[i].z); u.w = f2tf(pb[i].w);
                *(uint4*)&bBuf[buf][(f >> 3) * RW + (f & 7) * 4] = u;
            } else {          // transpose-store: B[k][n] -> Bs[n][k]
                int krow = f & 31, nc = (f >> 5) * 4;
                bBuf[buf][(nc+0) * RW + krow] = f2tf(pb[i].x);
                bBuf[buf][(nc+1) * RW + krow] = f2tf(pb[i].y);
                bBuf[buf][(nc+2) * RW + krow] = f2tf(pb[i].z);
                bBuf[buf][(nc+3) * RW + krow] = f2tf(pb[i].w);
            }
        }
    };

    const int T = Keff / BK;
    load_g(0);
    store_s(0);
    __syncthreads();

    for (int t = 0; t < T; t++) {
        const int cur = t & 1;
        if (t + 1 < T) load_g((t + 1) * BK);

        #pragma unroll
        for (int ks = 0; ks < 4; ks++) {
            const uint32_t kk = ks * 8;
            unsigned a[MT][4];
            #pragma unroll
            for (int mt = 0; mt < MT; mt++)
                ldm_x4(a[mt][0], a[mt][1], a[mt][2], a[mt][3],
                       aAdr[cur] + (laneA + mt * 16 * RW + kk) * 4);
            unsigned b[NT][2];
            #pragma unroll
            for (int ng = 0; ng < NG; ng++) {
                unsigned q0, q1, q2, q3;
                ldm_x4(q0, q1, q2, q3,
                       bAdr[cur] + (laneB + ng * 16 * RW + kk) * 4);
                b[2*ng  ][0] = q0; b[2*ng  ][1] = q2;
                b[2*ng+1][0] = q1; b[2*ng+1][1] = q3;
            }
            #pragma unroll
            for (int mt = 0; mt < MT; mt++)
                #pragma unroll
                for (int nt = 0; nt < NT; nt++)
                    mma_tf32(acc[mt][nt], a[mt], b[nt]);
        }

        if (t + 1 < T) store_s((t + 1) & 1);
        __syncthreads();
    }

    // ---- writeback ----
    #pragma unroll
    for (int mt = 0; mt < MT; mt++) {
        int r0 = m0 + wm0 + mt * 16 + gid;
        #pragma unroll
        for (int nt = 0; nt < NT; nt++) {
            int cc = n0 + wn0 + nt * 8 + tig * 2;
            if (CT) {
                C[(long)(cc    ) * ldc + r0    ] = acc[mt][nt][0] * alpha;
                C[(long)(cc + 1) * ldc + r0    ] = acc[mt][nt][1] * alpha;
                C[(long)(cc    ) * ldc + r0 + 8] = acc[mt][nt][2] * alpha;
                C[(long)(cc + 1) * ldc + r0 + 8] = acc[mt][nt][3] * alpha;
            } else {
                float2 v0 = make_float2(acc[mt][nt][0] * alpha, acc[mt][nt][1] * alpha);
                float2 v1 = make_float2(acc[mt][nt][2] * alpha, acc[mt][nt][3] * alpha);
                *(float2*)&C[(long)r0 * ldc + cc]       = v0;
                *(float2*)&C[(long)(r0 + 8) * ldc + cc] = v1;
            }
        }
    }
}

// ---------------- LayerNorm over L=512 ------------------------------------------
__global__ __launch_bounds__(256)
void ln_k(const float* __restrict__ c, float* __restrict__ ckv,
          float* __restrict__ out2,
          const float* __restrict__ gamma, const float* __restrict__ beta)
{
    __shared__ float red[256];
    const int r   = blockIdx.x;
    const int tid = threadIdx.x;
    const float* row = c + (long)r * L_;

    float a0 = row[tid], a1 = row[tid + 256];

    red[tid] = a0 + a1; __syncthreads();
    for (int s = 128; s > 0; s >>= 1) { if (tid < s) red[tid] += red[tid+s]; __syncthreads(); }
    float mu = red[0] * (1.0f / L_); __syncthreads();

    float d0 = a0 - mu, d1 = a1 - mu;
    red[tid] = d0*d0 + d1*d1; __syncthreads();
    for (int s = 128; s > 0; s >>= 1) { if (tid < s) red[tid] += red[tid+s]; __syncthreads(); }
    float rstd = rsqrtf(red[0] * (1.0f / L_) + 1e-5f);

    float y0 = d0 * rstd * gamma[tid]       + beta[tid];
    float y1 = d1 * rstd * gamma[tid + 256] + beta[tid + 256];

    long o = (long)r * L_;
    ckv[o + tid] = y0; ckv[o + tid + 256] = y1;
    if (out2) { out2[o + tid] = y0; out2[o + tid + 256] = y1; }
}

// ---------------- causal softmax over t, in place --------------------------------
__global__ __launch_bounds__(256)
void softmax_k(float* __restrict__ sc)
{
    __shared__ float red[256];
    const long r  = blockIdx.x;
    const int  s  = (int)(r % S_);
    const int tid = threadIdx.x;
    float* row = sc + r * (long)S_;

    float v[8];
    float mx = -INFINITY;
    #pragma unroll
    for (int i = 0; i < 8; i++) {
        int t = tid + i*256;
        v[i] = (t <= s) ? row[t] : -INFINITY;
        mx = fmaxf(mx, v[i]);
    }
    red[tid] = mx; __syncthreads();
    for (int k = 128; k > 0; k >>= 1) { if (tid < k) red[tid] = fmaxf(red[tid], red[tid+k]); __syncthreads(); }
    mx = red[0]; __syncthreads();

    float sum = 0.f;
    #pragma unroll
    for (int i = 0; i < 8; i++) {
        int t = tid + i*256;
        v[i] = (t <= s) ? __expf(v[i] - mx) : 0.f;
        sum += v[i];
    }
    red[tid] = sum; __syncthreads();
    for (int k = 128; k > 0; k >>= 1) { if (tid < k) red[tid] += red[tid+k]; __syncthreads(); }
    float inv = 1.0f / red[0];

    const int bound = ((s >> 7) + 1) << 7;   // zero-fill through the 128-wide diag tile
    #pragma unroll
    for (int i = 0; i < 8; i++) {
        int t = tid + i*256;
        if (t < bound) row[t] = (t <= s) ? v[i] * inv : 0.f;
    }
}

// ---------------- launch ---------------------------------------------------------
extern "C" void kernel_launch(void* const* d_in, const int* in_sizes, int n_in,
                              void* d_out, int out_size)
{
    const float* x      = (const float*)d_in[0];
    const float* W_q    = (const float*)d_in[1];
    const float* W_dkv  = (const float*)d_in[2];
    const float* W_uk   = (const float*)d_in[3];
    const float* W_uv   = (const float*)d_in[4];
    const float* W_o    = (const float*)d_in[5];
    const float* gamma  = (const float*)d_in[6];
    const float* beta   = (const float*)d_in[7];
    float* out = (float*)d_out;

    float *c, *ckv, *akT, *tmp, *sc, *vT, *ctx;
    cudaGetSymbolAddress((void**)&c,   g_c);
    cudaGetSymbolAddress((void**)&ckv, g_ckv);
    cudaGetSymbolAddress((void**)&akT, g_akT);
    cudaGetSymbolAddress((void**)&tmp, g_tmp);
    cudaGetSymbolAddress((void**)&sc,  g_sc);
    cudaGetSymbolAddress((void**)&vT,  g_vT);
    cudaGetSymbolAddress((void**)&ctx, g_ctx);

    float* out_ckv = (out_size >= NTOK*D_ + NTOK*L_) ? out + (long)NTOK*D_ : nullptr;

    // dynamic smem: 2*(128 + BN)*36 words * 4 B
    const int SM128 = 2 * (128 + 128) * 36 * 4;   // 73728 B
    const int SM64  = 2 * (128 + 64)  * 36 * 4;   // 55296 B
    cudaFuncSetAttribute(tc_gemm<128,true ,0,false>, cudaFuncAttributeMaxDynamicSharedMemorySize, SM128);
    cudaFuncSetAttribute(tc_gemm<128,false,0,true >, cudaFuncAttributeMaxDynamicSharedMemorySize, SM128);
    cudaFuncSetAttribute(tc_gemm<128,true ,1,false>, cudaFuncAttributeMaxDynamicSharedMemorySize, SM128);
    cudaFuncSetAttribute(tc_gemm<128,true ,0,true >, cudaFuncAttributeMaxDynamicSharedMemorySize, SM128);
    cudaFuncSetAttribute(tc_gemm<64 ,true ,2,false>, cudaFuncAttributeMaxDynamicSharedMemorySize, SM64);

    const dim3 blk(256);

    // K1: c = x @ W_dkv^T   [4096,512]
    tc_gemm<128,true,0,false><<<dim3(L_/128, NTOK/128, 1), blk, SM128>>>(
        x, W_dkv, c, NTOK, L_, D_, D_, D_, L_,
        0,0, 0,0, 0,0, 16, 1.0f);

    // K2: LayerNorm -> c_kv (and second output)
    ln_k<<<NTOK, 256>>>(c, ckv, out_ckv, gamma, beta);

    // K3: akT = (W_q @ W_uk)^T  via CT store. A=W_q [D,D], B=W_uk [D,L] (!BT)
    tc_gemm<128,false,0,true><<<dim3(L_/128, D_/128, 1), blk, SM128>>>(
        W_q, W_uk, akT, D_, L_, D_, D_, L_, D_,
        0,0, 0,0, 0,0, 16, 1.0f);

    // K4: tmp[b,s,h,:] = x[b,s,h*64:+64] @ akT[:, h*64:+64]^T   (batched over h)
    tc_gemm<128,true,0,false><<<dim3(L_/128, NTOK/128, H_), blk, SM128>>>(
        x, akT, tmp, NTOK, L_, DH_, D_, D_, H_*L_,
        0, DH_,                  // A: + h*64
        0, DH_,                  // B: akT + h*64
        0, L_,                   // C: + h*L
        16, 1.0f);

    // K5: scores = tmp @ c_kv^T / 8   (batched over b,h; causal block skip)
    tc_gemm<128,true,1,false><<<dim3(S_/128, S_/128, B_*H_), blk, SM128>>>(
        tmp, ckv, sc, S_, S_, L_, H_*L_, L_, S_,
        (long)S_*H_*L_, (long)L_,
        (long)S_*L_,    0,
        (long)H_*S_*S_, (long)S_*S_,
        H_, 0.125f);

    // K6: causal softmax, in place
    softmax_k<<<B_*H_*S_, 256>>>(sc);

    // K7: vT = (c_kv @ W_uv^T)^T  -> [D, NTOK] via CT store
    tc_gemm<128,true,0,true><<<dim3(D_/128, NTOK/128, 1), blk, SM128>>>(
        ckv, W_uv, vT, NTOK, D_, L_, L_, L_, NTOK,
        0,0, 0,0, 0,0, 16, 1.0f);

    // K8: ctx[b,:,h,:] = attn @ vT[h*64:+64, b*2048:+2048]^T  (batched; K clamped)
    tc_gemm<64,true,2,false><<<dim3(1, S_/128, B_*H_), blk, SM64>>>(
        sc, vT, ctx, S_, DH_, S_, S_, NTOK, D_,
        (long)H_*S_*S_, (long)S_*S_,           // A: b, h
        (long)S_,       (long)DH_*NTOK,        // B: vT + b*2048 cols + h*64 rows
        (long)S_*D_,    (long)DH_,             // C: b, h
        H_, 1.0f);

    // K9: out = ctx @ W_o^T
    tc_gemm<128,true,0,false><<<dim3(D_/128, NTOK/128, 1), blk, SM128>>>(
        ctx, W_o, out, NTOK, D_, D_, D_, D_, D_,
        0,0, 0,0, 0,0, 16, 1.0f);
}

// round 8
// speedup vs baseline: 2.0314x; 1.4144x over previous
#include <cuda_runtime.h>
#include <math.h>
#include <stdint.h>

// Problem constants
#define B_  2
#define S_  2048
#define D_  1024
#define H_  16
#define L_  512
#define DH_ 64
#define NTOK (B_*S_)          // 4096

// ---------------- scratch (device globals) --------------------------------------
__device__ float g_c    [NTOK * L_];                 // pre-LN latent (exact fp32)
__device__ float g_ckv  [NTOK * L_];                 // LN latent, tf32 bits
__device__ float g_akT  [L_ * D_];                   // absorbed K^T [L,D], tf32
__device__ float g_tmp  [(size_t)B_ * S_ * H_ * L_]; // q_eff, tf32
__device__ float g_sc   [(size_t)B_ * H_ * S_ * S_]; // scores fp32 / attn tf32
__device__ float g_vT   [(size_t)D_ * NTOK];         // V^T [D,NTOK], tf32
__device__ float g_ctx  [NTOK * D_];                 // context, tf32
__device__ float g_xtf  [NTOK * D_];                 // x, tf32
__device__ float g_wdkv [L_ * D_];                   // W_dkv, tf32
__device__ float g_wq   [D_ * D_];                   // W_q, tf32
__device__ float g_wukT [L_ * D_];                   // W_uk^T [L,D], tf32
__device__ float g_wuv  [D_ * L_];                   // W_uv, tf32
__device__ float g_wo   [D_ * D_];                   // W_o, tf32

// ---------------- helpers ---------------------------------------------------------
__device__ __forceinline__ uint32_t s2u(const void* p) {
    uint32_t a;
    asm("{ .reg .u64 t; cvta.to.shared.u64 t, %1; cvt.u32.u64 %0, t; }"
        : "=r"(a) : "l"(p));
    return a;
}
__device__ __forceinline__ unsigned f2tf(float f) {
    unsigned u;
    asm("cvt.rna.tf32.f32 %0, %1;" : "=r"(u) : "f"(f));
    return u;
}
__device__ __forceinline__ float f2tff(float f) {
    return __uint_as_float(f2tf(f));
}
__device__ __forceinline__ void cp16(uint32_t dst, const void* src) {
    asm volatile("cp.async.cg.shared.global [%0], [%1], 16;"
                 :: "r"(dst), "l"(src) : "memory");
}
__device__ __forceinline__ void ldm_x4(unsigned &r0, unsigned &r1, unsigned &r2,
                                       unsigned &r3, uint32_t addr) {
    asm volatile("ldmatrix.sync.aligned.m8n8.x4.shared.b16 {%0,%1,%2,%3}, [%4];"
                 : "=r"(r0), "=r"(r1), "=r"(r2), "=r"(r3) : "r"(addr));
}
__device__ __forceinline__ void mma_tf32(float (&c)[4], const unsigned (&a)[4],
                                         const unsigned (&b)[2]) {
    asm volatile(
        "mma.sync.aligned.m16n8k8.row.col.f32.tf32.tf32.f32 "
        "{%0,%1,%2,%3}, {%4,%5,%6,%7}, {%8,%9}, {%0,%1,%2,%3};"
        : "+f"(c[0]), "+f"(c[1]), "+f"(c[2]), "+f"(c[3])
        : "r"(a[0]), "r"(a[1]), "r"(a[2]), "r"(a[3]), "r"(b[0]), "r"(b[1]));
}

// ---------------- tf32 mma.sync GEMM, cp.async 3-stage, pre-converted inputs ------
// C[m,n] = alpha * sum_k A[m,k] * B[n,k]   (A,B row-major K-major, tf32 bits)
// CT: store transposed C[n*ldc+m]. TFOUT: round stores to tf32 bits.
// CAUSAL: 0 none, 1 skip blocks n0 > m0+BM-1, 2 clamp K to m0+BM.
// BM=128, BK=32, 256 threads = 8 warps (2M x 4N), warp tile 64 x BN/4.
// Smem rows are 128B (32 tf32) with XOR-chunk swizzle: chunk' = chunk ^ (row&7).
// Pipeline invariant: iteration t needs group t complete. On the last iteration
// no new group is issued, so wait_group(0) there (wait_group(1) would be a no-op
// with only one group outstanding -> race on the final k-tile).
template<int BN, int CAUSAL, bool CT, bool TFOUT>
__global__ __launch_bounds__(256, 2)
void tc_gemm(const float* __restrict__ A, const float* __restrict__ B,
             float* __restrict__ C,
             int M, int N, int K, int lda, int ldb, int ldc,
             long sA1, long sA2, long sB1, long sB2, long sC1, long sC2,
             int zdiv, float alpha)
{
    constexpr int BM = 128, BK = 32, STAGES = 3;
    constexpr int MT = 4;                 // m16 tiles per warp
    constexpr int NT = BN / 32;           // n8 tiles per warp
    constexpr int NG = NT / 2;            // n16 ldmatrix groups
    constexpr int LA = BM * 8 / 256;      // 16B chunks per thread (A)
    constexpr int LB = BN * 8 / 256;      // (B)
    constexpr int STG_B = (BM + BN) * 128;   // stage bytes

    extern __shared__ __align__(128) char sm[];
    const uint32_t smu = s2u(sm);

    const int z = blockIdx.z;
    const int zhi = z / zdiv, zlo = z % zdiv;
    A += (long)zhi * sA1 + (long)zlo * sA2;
    B += (long)zhi * sB1 + (long)zlo * sB2;
    C += (long)zhi * sC1 + (long)zlo * sC2;

    const int m0 = blockIdx.y * BM;
    const int n0 = blockIdx.x * BN;
    if (CAUSAL == 1 && n0 > m0 + BM - 1) return;
    int Keff = K;
    if (CAUSAL == 2) Keff = min(K, m0 + BM);

    const int tid  = threadIdx.x;
    const int warp = tid >> 5;
    const int lane = tid & 31;
    const int gid  = lane >> 2;
    const int tig  = lane & 3;
    const int wm0  = (warp & 1) * 64;
    const int wn0  = (warp >> 1) * (BN / 4);

    // ldmatrix per-lane addressing
    const uint32_t lrow  = ((lane >> 3) & 1) * 8 + (lane & 7);
    const uint32_t chsel = (lane >> 4);          // 0/1: k 0-3 vs 4-7
    const uint32_t swl   = lane & 7;             // row&7 (16-row steps keep it)
    const uint32_t aRow = (wm0 + lrow) * 128;
    const uint32_t bRow = (wn0 + lrow) * 128;

    // cp.async per-thread chunk coordinates
    int ar[LA]; uint32_t ad[LA]; int aco[LA];
    #pragma unroll
    for (int i = 0; i < LA; i++) {
        int f = tid + i * 256, row = f >> 3, ch = f & 7;
        ar[i] = row; aco[i] = ch * 4;
        ad[i] = row * 128 + ((ch ^ (row & 7)) << 4);
    }
    int br[LB]; uint32_t bd[LB]; int bco[LB];
    #pragma unroll
    for (int i = 0; i < LB; i++) {
        int f = tid + i * 256, row = f >> 3, ch = f & 7;
        br[i] = row; bco[i] = ch * 4;
        bd[i] = BM * 128 + row * 128 + ((ch ^ (row & 7)) << 4);
    }

    float acc[MT][NT][4];
    #pragma unroll
    for (int i = 0; i < MT; i++)
        #pragma unroll
        for (int j = 0; j < NT; j++)
            #pragma unroll
            for (int r = 0; r < 4; r++) acc[i][j][r] = 0.f;

    const int T = Keff / BK;

    auto issue_stage = [&](int t) {
        const int k0 = t * BK;
        const uint32_t sb = smu + (t % STAGES) * STG_B;
        #pragma unroll
        for (int i = 0; i < LA; i++)
            cp16(sb + ad[i], &A[(long)(m0 + ar[i]) * lda + k0 + aco[i]]);
        #pragma unroll
        for (int i = 0; i < LB; i++)
            cp16(sb + bd[i], &B[(long)(n0 + br[i]) * ldb + k0 + bco[i]]);
        asm volatile("cp.async.commit_group;" ::: "memory");
    };

    int fetch = 0;
    #pragma unroll
    for (int s = 0; s < STAGES - 1; s++)
        if (fetch < T) { issue_stage(fetch); fetch++; }

    for (int t = 0; t < T; t++) {
        if (t == T - 1)
            asm volatile("cp.async.wait_group 0;" ::: "memory");
        else
            asm volatile("cp.async.wait_group %0;" :: "n"(STAGES - 2) : "memory");
        __syncthreads();
        if (fetch < T) { issue_stage(fetch); fetch++; }

        const uint32_t sb  = smu + (t % STAGES) * STG_B;
        const uint32_t sbB = sb + BM * 128;
        #pragma unroll
        for (int ks = 0; ks < 4; ks++) {
            const uint32_t chx = (((2u * ks + chsel) ^ swl) << 4);
            unsigned a[MT][4];
            #pragma unroll
            for (int mt = 0; mt < MT; mt++)
                ldm_x4(a[mt][0], a[mt][1], a[mt][2], a[mt][3],
                       sb + aRow + mt * 16 * 128 + chx);
            unsigned b[NT][2];
            #pragma unroll
            for (int ng = 0; ng < NG; ng++) {
                unsigned q0, q1, q2, q3;
                ldm_x4(q0, q1, q2, q3, sbB + bRow + ng * 16 * 128 + chx);
                b[2*ng  ][0] = q0; b[2*ng  ][1] = q2;
                b[2*ng+1][0] = q1; b[2*ng+1][1] = q3;
            }
            #pragma unroll
            for (int mt = 0; mt < MT; mt++)
                #pragma unroll
                for (int nt = 0; nt < NT; nt++)
                    mma_tf32(acc[mt][nt], a[mt], b[nt]);
        }
        __syncthreads();
    }

    // ---- writeback ----
    #pragma unroll
    for (int mt = 0; mt < MT; mt++) {
        int r0 = m0 + wm0 + mt * 16 + gid;
        #pragma unroll
        for (int nt = 0; nt < NT; nt++) {
            int cc = n0 + wn0 + nt * 8 + tig * 2;
            float o0 = acc[mt][nt][0] * alpha, o1 = acc[mt][nt][1] * alpha;
            float o2 = acc[mt][nt][2] * alpha, o3 = acc[mt][nt][3] * alpha;
            if (TFOUT) { o0 = f2tff(o0); o1 = f2tff(o1); o2 = f2tff(o2); o3 = f2tff(o3); }
            if (CT) {
                C[(long)(cc    ) * ldc + r0    ] = o0;
                C[(long)(cc + 1) * ldc + r0    ] = o1;
                C[(long)(cc    ) * ldc + r0 + 8] = o2;
                C[(long)(cc + 1) * ldc + r0 + 8] = o3;
            } else {
                *(float2*)&C[(long)r0 * ldc + cc]       = make_float2(o0, o1);
                *(float2*)&C[(long)(r0 + 8) * ldc + cc] = make_float2(o2, o3);
            }
        }
    }
}

// ---------------- elementwise tf32 convert ----------------------------------------
__global__ __launch_bounds__(256)
void cvt_k(const float4* __restrict__ in, float4* __restrict__ out, int n4)
{
    int i = blockIdx.x * 256 + threadIdx.x;
    if (i < n4) {
        float4 v = in[i];
        v.x = f2tff(v.x); v.y = f2tff(v.y); v.z = f2tff(v.z); v.w = f2tff(v.w);
        out[i] = v;
    }
}

// ---------------- transpose + tf32 convert:  out[c*R + r] = tf(in[r*C + c]) -------
__global__ __launch_bounds__(256)
void trcvt_k(const float* __restrict__ in, float* __restrict__ out, int R, int C)
{
    __shared__ float t[32][33];
    const int r0 = blockIdx.y * 32, c0 = blockIdx.x * 32;
    const int tx = threadIdx.x & 31, ty = threadIdx.x >> 5;   // 32x8
    #pragma unroll
    for (int j = 0; j < 32; j += 8)
        t[ty + j][tx] = in[(long)(r0 + ty + j) * C + c0 + tx];
    __syncthreads();
    #pragma unroll
    for (int j = 0; j < 32; j += 8)
        out[(long)(c0 + ty + j) * R + r0 + tx] = f2tff(t[tx][ty + j]);
}

// ---------------- LayerNorm over L=512 ------------------------------------------
__global__ __launch_bounds__(256)
void ln_k(const float* __restrict__ c, float* __restrict__ ckv,
          float* __restrict__ out2,
          const float* __restrict__ gamma, const float* __restrict__ beta)
{
    __shared__ float red[256];
    const int r   = blockIdx.x;
    const int tid = threadIdx.x;
    const float* row = c + (long)r * L_;

    float a0 = row[tid], a1 = row[tid + 256];

    red[tid] = a0 + a1; __syncthreads();
    for (int s = 128; s > 0; s >>= 1) { if (tid < s) red[tid] += red[tid+s]; __syncthreads(); }
    float mu = red[0] * (1.0f / L_); __syncthreads();

    float d0 = a0 - mu, d1 = a1 - mu;
    red[tid] = d0*d0 + d1*d1; __syncthreads();
    for (int s = 128; s > 0; s >>= 1) { if (tid < s) red[tid] += red[tid+s]; __syncthreads(); }
    float rstd = rsqrtf(red[0] * (1.0f / L_) + 1e-5f);

    float y0 = d0 * rstd * gamma[tid]       + beta[tid];
    float y1 = d1 * rstd * gamma[tid + 256] + beta[tid + 256];

    long o = (long)r * L_;
    ckv[o + tid] = f2tff(y0); ckv[o + tid + 256] = f2tff(y1);   // GEMM consumer
    if (out2) { out2[o + tid] = y0; out2[o + tid + 256] = y1; } // exact output
}

// ---------------- causal softmax over t, in place; writes tf32 attn ---------------
__global__ __launch_bounds__(256)
void softmax_k(float* __restrict__ sc)
{
    __shared__ float red[256];
    const long r  = blockIdx.x;
    const int  s  = (int)(r % S_);
    const int tid = threadIdx.x;
    float* row = sc + r * (long)S_;

    float v[8];
    float mx = -INFINITY;
    #pragma unroll
    for (int i = 0; i < 8; i++) {
        int t = tid + i*256;
        v[i] = (t <= s) ? row[t] : -INFINITY;
        mx = fmaxf(mx, v[i]);
    }
    red[tid] = mx; __syncthreads();
    for (int k = 128; k > 0; k >>= 1) { if (tid < k) red[tid] = fmaxf(red[tid], red[tid+k]); __syncthreads(); }
    mx = red[0]; __syncthreads();

    float sum = 0.f;
    #pragma unroll
    for (int i = 0; i < 8; i++) {
        int t = tid + i*256;
        v[i] = (t <= s) ? __expf(v[i] - mx) : 0.f;
        sum += v[i];
    }
    red[tid] = sum; __syncthreads();
    for (int k = 128; k > 0; k >>= 1) { if (tid < k) red[tid] += red[tid+k]; __syncthreads(); }
    float inv = 1.0f / red[0];

    const int bound = ((s >> 7) + 1) << 7;   // zero-fill through the 128-wide diag tile
    #pragma unroll
    for (int i = 0; i < 8; i++) {
        int t = tid + i*256;
        if (t < bound) row[t] = (t <= s) ? f2tff(v[i] * inv) : 0.f;
    }
}

// ---------------- launch ---------------------------------------------------------
extern "C" void kernel_launch(void* const* d_in, const int* in_sizes, int n_in,
                              void* d_out, int out_size)
{
    const float* x      = (const float*)d_in[0];
    const float* W_q    = (const float*)d_in[1];
    const float* W_dkv  = (const float*)d_in[2];
    const float* W_uk   = (const float*)d_in[3];
    const float* W_uv   = (const float*)d_in[4];
    const float* W_o    = (const float*)d_in[5];
    const float* gamma  = (const float*)d_in[6];
    const float* beta   = (const float*)d_in[7];
    float* out = (float*)d_out;

    float *c, *ckv, *akT, *tmp, *sc, *vT, *ctx;
    float *xtf, *wdkv, *wq, *wukT, *wuv, *wo;
    cudaGetSymbolAddress((void**)&c,    g_c);
    cudaGetSymbolAddress((void**)&ckv,  g_ckv);
    cudaGetSymbolAddress((void**)&akT,  g_akT);
    cudaGetSymbolAddress((void**)&tmp,  g_tmp);
    cudaGetSymbolAddress((void**)&sc,   g_sc);
    cudaGetSymbolAddress((void**)&vT,   g_vT);
    cudaGetSymbolAddress((void**)&ctx,  g_ctx);
    cudaGetSymbolAddress((void**)&xtf,  g_xtf);
    cudaGetSymbolAddress((void**)&wdkv, g_wdkv);
    cudaGetSymbolAddress((void**)&wq,   g_wq);
    cudaGetSymbolAddress((void**)&wukT, g_wukT);
    cudaGetSymbolAddress((void**)&wuv,  g_wuv);
    cudaGetSymbolAddress((void**)&wo,   g_wo);

    float* out_ckv = (out_size >= NTOK*D_ + NTOK*L_) ? out + (long)NTOK*D_ : nullptr;

    const int SM128 = 3 * (128 + 128) * 128;   // 98304 B
    const int SM64  = 3 * (128 + 64)  * 128;   // 73728 B
    cudaFuncSetAttribute(tc_gemm<128,0,false,false>, cudaFuncAttributeMaxDynamicSharedMemorySize, SM128);
    cudaFuncSetAttribute(tc_gemm<128,0,true ,true >, cudaFuncAttributeMaxDynamicSharedMemorySize, SM128);
    cudaFuncSetAttribute(tc_gemm<128,0,false,true >, cudaFuncAttributeMaxDynamicSharedMemorySize, SM128);
    cudaFuncSetAttribute(tc_gemm<128,1,false,false>, cudaFuncAttributeMaxDynamicSharedMemorySize, SM128);
    cudaFuncSetAttribute(tc_gemm<64 ,2,false,true >, cudaFuncAttributeMaxDynamicSharedMemorySize, SM64);

    const dim3 blk(256);

    // P0: convert inputs to tf32 bit patterns
    cvt_k<<<NTOK*D_/1024, 256>>>((const float4*)x,     (float4*)xtf,  NTOK*D_/4);
    cvt_k<<<L_*D_/1024,   256>>>((const float4*)W_dkv, (float4*)wdkv, L_*D_/4);
    cvt_k<<<D_*D_/1024,   256>>>((const float4*)W_q,   (float4*)wq,   D_*D_/4);
    cvt_k<<<D_*L_/1024,   256>>>((const float4*)W_uv,  (float4*)wuv,  D_*L_/4);
    cvt_k<<<D_*D_/1024,   256>>>((const float4*)W_o,   (float4*)wo,   D_*D_/4);
    trcvt_k<<<dim3(L_/32, D_/32), 256>>>(W_uk, wukT, D_, L_);   // [D,L] -> [L,D]

    // K1: c = x @ W_dkv^T   (exact fp32 out -> LN)
    tc_gemm<128,0,false,false><<<dim3(L_/128, NTOK/128, 1), blk, SM128>>>(
        xtf, wdkv, c, NTOK, L_, D_, D_, D_, L_,
        0,0, 0,0, 0,0, 16, 1.0f);

    // K2: LayerNorm -> ckv (tf32) + exact second output
    ln_k<<<NTOK, 256>>>(c, ckv, out_ckv, gamma, beta);

    // K3: akT = (W_q @ W_uk)^T  [L,D], tf32
    tc_gemm<128,0,true,true><<<dim3(L_/128, D_/128, 1), blk, SM128>>>(
        wq, wukT, akT, D_, L_, D_, D_, D_, D_,
        0,0, 0,0, 0,0, 16, 1.0f);

    // K4: tmp[b,s,h,:] = x[b,s,h*64:+64] @ akT[:, h*64:+64]^T  (batched over h)
    tc_gemm<128,0,false,true><<<dim3(L_/128, NTOK/128, H_), blk, SM128>>>(
        xtf, akT, tmp, NTOK, L_, DH_, D_, D_, H_*L_,
        0, DH_,
        0, DH_,
        0, L_,
        16, 1.0f);

    // K5: scores = tmp @ ckv^T / 8  (batched b,h; causal block skip; fp32 out)
    tc_gemm<128,1,false,false><<<dim3(S_/128, S_/128, B_*H_), blk, SM128>>>(
        tmp, ckv, sc, S_, S_, L_, H_*L_, L_, S_,
        (long)S_*H_*L_, (long)L_,
        (long)S_*L_,    0,
        (long)H_*S_*S_, (long)S_*S_,
        H_, 0.125f);

    // K6: causal softmax (writes tf32 attn)
    softmax_k<<<B_*H_*S_, 256>>>(sc);

    // K7: vT = (ckv @ W_uv^T)^T  [D,NTOK], tf32
    tc_gemm<128,0,true,true><<<dim3(D_/128, NTOK/128, 1), blk, SM128>>>(
        ckv, wuv, vT, NTOK, D_, L_, L_, L_, NTOK,
        0,0, 0,0, 0,0, 16, 1.0f);

    // K8: ctx[b,:,h,:] = attn @ vT[h*64:+64, b*2048:+2048]^T  (K clamped), tf32
    tc_gemm<64,2,false,true><<<dim3(1, S_/128, B_*H_), blk, SM64>>>(
        sc, vT, ctx, S_, DH_, S_, S_, NTOK, D_,
        (long)H_*S_*S_, (long)S_*S_,
        (long)S_,       (long)DH_*NTOK,
        (long)S_*D_,    (long)DH_,
        H_, 1.0f);

    // K9: out = ctx @ W_o^T  (exact fp32 out)
    tc_gemm<128,0,false,false><<<dim3(D_/128, NTOK/128, 1), blk, SM128>>>(
        ctx, wo, out, NTOK, D_, D_, D_, D_, D_,
        0,0, 0,0, 0,0, 16, 1.0f);
}